// round 13
// baseline (speedup 1.0000x reference)
#include <cuda_runtime.h>
#include <math.h>
#include <stdint.h>

// ---------------------------------------------------------------------------
// Problem constants (fixed instance: B=4096, D=512). Scratch lives in
// __device__ globals (no allocations allowed). sim matrix is NEVER
// materialized: the GEMM epilogue reduces each tile into per-anchor
// weighted-exp partials for both directions.
// ---------------------------------------------------------------------------
#define BMAX 4096
#define DMAX 512
#define TEMP_INV (1.0f / 0.07f)
#define MARGIN 0.2f
#define MAXP 64
#define NBUCK 2048
#define NT_MAX 32                    // BMAX/128 partial tiles per anchor

static __device__ float g_vn[BMAX * DMAX];       // normalized vision (tf32)
static __device__ float g_tn[BMAX * DMAX];       // normalized text (tf32)
static __device__ int   g_ids32[BMAX];           // normalized match ids
static __device__ int   g_bcnt[NBUCK];           // bucket counts / cursors
static __device__ int   g_bstart[NBUCK + 1];     // bucket start offsets
static __device__ int   g_bitem[BMAX];           // row indices by bucket
static __device__ int   g_np[BMAX];              // positives per row
static __device__ float g_mean2[2 * BMAX];       // mean_pos per (dir, anchor)
static __device__ float g_pd0[BMAX * MAXP];      // positive dots dir0 (vn_r . tn_j)
static __device__ float g_pd1[BMAX * MAXP];      // positive dots dir1 (vn_j . tn_r)
static __device__ float g_prow[(size_t)BMAX * NT_MAX];  // dir0 exp partials
static __device__ float g_pcol[(size_t)BMAX * NT_MAX];  // dir1 exp partials
static __device__ float g_lossA[BMAX];
static __device__ float g_lossB[BMAX];
static __device__ float g_cnt[BMAX];

// ---------------------------------------------------------------------------
// Reductions
// ---------------------------------------------------------------------------
__device__ __forceinline__ float warpSum(float v) {
#pragma unroll
    for (int o = 16; o; o >>= 1) v += __shfl_down_sync(0xffffffffu, v, o);
    return v;
}

__device__ __forceinline__ float blockSum(float v, float* sred, int nwarp) {
    v = warpSum(v);
    int w = threadIdx.x >> 5, l = threadIdx.x & 31;
    if (l == 0) sred[w] = v;
    __syncthreads();
    if (threadIdx.x < 32) {
        float x = (l < nwarp) ? sred[l] : 0.0f;
        x = warpSum(x);
        if (l == 0) sred[0] = x;
    }
    __syncthreads();
    float r = sred[0];
    __syncthreads();
    return r;
}

// ---------------------------------------------------------------------------
// tf32 round-to-nearest helper
// ---------------------------------------------------------------------------
__device__ __forceinline__ float to_tf32(float x) {
    uint32_t u;
    asm("cvt.rna.tf32.f32 %0, %1;" : "=r"(u) : "f"(x));
    return __uint_as_float(u);
}

// ---------------------------------------------------------------------------
// 1. Combined pre-pass, grid (B, 3), 256 threads:
//    y = 0/1 : L2-normalize row x of vision/text (single float2 pass).
//    y = 2   : block x == 0 builds the id table (dtype detect + normalize to
//              int32 + bucket table); all other x exit.
// ---------------------------------------------------------------------------
__global__ __launch_bounds__(256) void k_pre(const float* __restrict__ vis,
                                             const float* __restrict__ txt,
                                             const int* __restrict__ w,
                                             int n, int D) {
    int tid = threadIdx.x;
    if (blockIdx.y < 2) {
        __shared__ float sred[8];
        int row = blockIdx.x, which = blockIdx.y;
        const float* in = which ? txt : vis;
        float* out = which ? g_tn : g_vn;
        const float* r = in + (size_t)row * D;
        float* wr = out + (size_t)row * D;
        float ss = 0.0f;
        for (int j = tid * 2; j < D; j += 512) {
            float2 v = *(const float2*)&r[j];
            ss += v.x * v.x + v.y * v.y;
        }
        float tot = blockSum(ss, sred, 8);
        float inv = 1.0f / fmaxf(sqrtf(tot), 1e-12f);
        for (int j = tid * 2; j < D; j += 512) {
            float2 v = *(const float2*)&r[j];
            v.x = to_tf32(v.x * inv); v.y = to_tf32(v.y * inv);
            *(float2*)&wr[j] = v;
        }
        return;
    }
    if (blockIdx.x != 0) return;

    // ---- id-table build (single block) ----
    __shared__ int flag;
    __shared__ int warp_tot[8];
    __shared__ int warp_base[8];
    if (tid == 0) flag = 0;
    __syncthreads();
    for (int j = tid * 2 + 1; j < n; j += 512)
        if (w[j] != 0) flag = 1;   // benign race
    __syncthreads();
    int mode = flag ? 0 : 1;       // 0 = int32, 1 = int64
    for (int j = tid; j < n; j += 256)
        g_ids32[j] = mode ? (int)((const long long*)w)[j] : w[j];
    for (int b = tid; b < NBUCK; b += 256) g_bcnt[b] = 0;
    __syncthreads();
    for (int j = tid; j < n; j += 256)
        atomicAdd(&g_bcnt[g_ids32[j] & (NBUCK - 1)], 1);
    __syncthreads();
    int base = tid * (NBUCK / 256);
    int pre[NBUCK / 256];
    int loc = 0;
#pragma unroll
    for (int k = 0; k < NBUCK / 256; k++) { pre[k] = loc; loc += g_bcnt[base + k]; }
    int lane = tid & 31, wd = tid >> 5;
    int v = loc;
#pragma unroll
    for (int o = 1; o < 32; o <<= 1) {
        int t = __shfl_up_sync(0xffffffffu, v, o);
        if (lane >= o) v += t;
    }
    if (lane == 31) warp_tot[wd] = v;
    __syncthreads();
    if (tid == 0) {
        int a = 0;
        for (int i = 0; i < 8; i++) { warp_base[i] = a; a += warp_tot[i]; }
    }
    __syncthreads();
    int excl = warp_base[wd] + v - loc;
#pragma unroll
    for (int k = 0; k < NBUCK / 256; k++) g_bstart[base + k] = excl + pre[k];
    if (tid == 0) g_bstart[NBUCK] = n;
    __syncthreads();
    for (int b = tid; b < NBUCK; b += 256) g_bcnt[b] = g_bstart[b];
    __syncthreads();
    for (int j = tid; j < n; j += 256) {
        int b = g_ids32[j] & (NBUCK - 1);
        int p = atomicAdd(&g_bcnt[b], 1);
        g_bitem[p] = j;
    }
}

// ---------------------------------------------------------------------------
// 2. Pairs: one block (128 threads) per anchor row. Finds positives via the
//    bucket table (sorted by position -> deterministic), computes their dot
//    products for both directions, and the per-direction mean_pos.
// ---------------------------------------------------------------------------
__global__ __launch_bounds__(128) void k_pairs(int N, int D) {
    __shared__ float sred[4];
    __shared__ int s_pos[MAXP];
    __shared__ int s_np;
    int r = blockIdx.x;
    int tid = threadIdx.x;
    int myid = g_ids32[r];

    if (tid == 0) {
        int b = myid & (NBUCK - 1);
        int np = 0;
        for (int p = g_bstart[b]; p < g_bstart[b + 1]; p++) {
            int j = g_bitem[p];
            if (g_ids32[j] == myid && np < MAXP) s_pos[np++] = j;
        }
        for (int i = 1; i < np; i++) {           // insertion sort by position
            int x = s_pos[i], k = i - 1;
            while (k >= 0 && s_pos[k] > x) { s_pos[k + 1] = s_pos[k]; k--; }
            s_pos[k + 1] = x;
        }
        s_np = np;
    }
    __syncthreads();
    int np = s_np;
    float m0 = 0.0f, m1 = 0.0f;
    for (int k = 0; k < np; k++) {
        int j = s_pos[k];
        float p0 = 0.0f, p1 = 0.0f;
        for (int d = tid; d < D / 4; d += 128) {
            float4 vr = ((const float4*)&g_vn[(size_t)r * D])[d];
            float4 tj = ((const float4*)&g_tn[(size_t)j * D])[d];
            p0 += vr.x * tj.x + vr.y * tj.y + vr.z * tj.z + vr.w * tj.w;
            float4 vj = ((const float4*)&g_vn[(size_t)j * D])[d];
            float4 tr = ((const float4*)&g_tn[(size_t)r * D])[d];
            p1 += vj.x * tr.x + vj.y * tr.y + vj.z * tr.z + vj.w * tr.w;
        }
        float d0 = blockSum(p0, sred, 4);
        float d1 = blockSum(p1, sred, 4);
        if (tid == 0) { g_pd0[r * MAXP + k] = d0; g_pd1[r * MAXP + k] = d1; }
        m0 += d0; m1 += d1;
    }
    if (tid == 0) {
        float fn = fmaxf((float)np, 1.0f);
        g_mean2[r] = m0 / fn;
        g_mean2[BMAX + r] = m1 / fn;
        g_np[r] = np;
        g_cnt[r] = (float)np;
    }
}

// ---------------------------------------------------------------------------
// 3. Tensor-core GEMM NT (tf32 via mma.sync + ldmatrix) with FUSED loss
//    reduction epilogue. MMA asm is intentionally NON-volatile: it is a pure
//    register function, and leaving it schedulable lets ptxas hoist the next
//    kk's ldmatrix loads over the current MMA block (software pipelining).
// ---------------------------------------------------------------------------
#define SMS 36
#define STAGE_F (2 * 128 * SMS)
#define TRS 133
#define GEMM_SMEM (2 * STAGE_F * 4)   // 73728 B >= epilogue 128*133*4 = 68096

__device__ __forceinline__ void cp16s(uint32_t dst, const float* src) {
    asm volatile("cp.async.cg.shared.global [%0], [%1], 16;" :: "r"(dst), "l"(src));
}

__device__ __forceinline__ void ldm_x4(uint32_t* r, uint32_t addr) {
    asm volatile("ldmatrix.sync.aligned.m8n8.x4.shared.b16 {%0,%1,%2,%3}, [%4];"
                 : "=r"(r[0]), "=r"(r[1]), "=r"(r[2]), "=r"(r[3]) : "r"(addr));
}

// Non-volatile MMA: schedulable by the compiler.
__device__ __forceinline__ void mma_tf32(float* c, const uint32_t* a,
                                         uint32_t b0, uint32_t b1) {
    asm("mma.sync.aligned.m16n8k8.row.col.f32.tf32.tf32.f32 "
        "{%0,%1,%2,%3}, {%4,%5,%6,%7}, {%8,%9}, {%0,%1,%2,%3};"
        : "+f"(c[0]), "+f"(c[1]), "+f"(c[2]), "+f"(c[3])
        : "r"(a[0]), "r"(a[1]), "r"(a[2]), "r"(a[3]), "r"(b0), "r"(b1));
}

__global__ __launch_bounds__(256, 2) void k_gemm_tf32(int N, int D) {
    extern __shared__ float sm[];
    __shared__ float rp[256];
    uint32_t smb = (uint32_t)__cvta_generic_to_shared(sm);

    const float* __restrict__ A = g_vn;
    const float* __restrict__ Bm = g_tn;
    int tid = threadIdx.x;
    int wid = tid >> 5, lane = tid & 31;
    int mo = (wid >> 2) * 64;
    int no = (wid & 3) * 32;
    int row0 = blockIdx.y * 128, col0 = blockIdx.x * 128;

    int tile = lane >> 3, trow = lane & 7;
    int ld_row = trow + (tile & 1) * 8;
    int ld_kof = (tile >> 1) * 4;

    float acc[4][4][4];
#pragma unroll
    for (int ms = 0; ms < 4; ms++)
#pragma unroll
        for (int ns = 0; ns < 4; ns++)
#pragma unroll
            for (int q = 0; q < 4; q++) acc[ms][ns][q] = 0.0f;

    const int KT = D >> 5;

#define FILL(sidx, kt_) do {                                                   \
        uint32_t sa = smb + (uint32_t)(sidx) * (STAGE_F * 4);                  \
        uint32_t sb = sa + 128 * SMS * 4;                                      \
        int kb = (kt_) << 5;                                                   \
        _Pragma("unroll")                                                      \
        for (int q = 0; q < 4; q++) {                                          \
            int f = tid + q * 256;                                             \
            int rr = f >> 3, c16 = f & 7;                                      \
            cp16s(sa + (uint32_t)(rr * SMS + c16 * 4) * 4,                     \
                  &A[(size_t)(row0 + rr) * D + kb + c16 * 4]);                 \
            cp16s(sb + (uint32_t)(rr * SMS + c16 * 4) * 4,                     \
                  &Bm[(size_t)(col0 + rr) * D + kb + c16 * 4]);                \
        }                                                                      \
        asm volatile("cp.async.commit_group;");                                \
    } while (0)

    FILL(0, 0);
    if (KT > 1) FILL(1, 1);

    for (int kt = 0; kt < KT; kt++) {
        int s = kt & 1;
        if (kt + 1 < KT) asm volatile("cp.async.wait_group 1;");
        else             asm volatile("cp.async.wait_group 0;");
        __syncthreads();

        uint32_t sa = smb + (uint32_t)s * (STAGE_F * 4);
        uint32_t sb = sa + 128 * SMS * 4;
        uint32_t a_base = sa + (uint32_t)((mo + ld_row) * SMS + ld_kof) * 4;
        uint32_t b_base = sb + (uint32_t)((no + ld_row) * SMS + ld_kof) * 4;

#pragma unroll
        for (int kk = 0; kk < 4; kk++) {
            uint32_t a[4][4], b[2][4];
#pragma unroll
            for (int ms = 0; ms < 4; ms++)
                ldm_x4(a[ms], a_base + (uint32_t)(ms * 16 * SMS + kk * 8) * 4);
#pragma unroll
            for (int n2 = 0; n2 < 2; n2++)
                ldm_x4(b[n2], b_base + (uint32_t)(n2 * 16 * SMS + kk * 8) * 4);
#pragma unroll
            for (int ms = 0; ms < 4; ms++)
#pragma unroll
                for (int n2 = 0; n2 < 2; n2++) {
                    mma_tf32(acc[ms][n2 * 2],     a[ms], b[n2][0], b[n2][2]);
                    mma_tf32(acc[ms][n2 * 2 + 1], a[ms], b[n2][1], b[n2][3]);
                }
        }
        __syncthreads();
        if (kt + 2 < KT) FILL(s, kt + 2);
    }

    // ---- Fused epilogue: stage tile, reduce both directions ----
    float* tr = sm;   // stage smem fully consumed (results in regs)
    int lq = lane >> 2, lm4 = lane & 3;
#pragma unroll
    for (int ms = 0; ms < 4; ms++) {
        int r = mo + ms * 16 + lq;
#pragma unroll
        for (int ns = 0; ns < 4; ns++) {
            int c = no + ns * 8 + 2 * lm4;
            tr[r * TRS + c]           = acc[ms][ns][0];
            tr[r * TRS + c + 1]       = acc[ms][ns][1];
            tr[(r + 8) * TRS + c]     = acc[ms][ns][2];
            tr[(r + 8) * TRS + c + 1] = acc[ms][ns][3];
        }
    }
    __syncthreads();

    // Row pass (dir 0): anchor = vision row row0+r.
    {
        int r = tid >> 1, h = tid & 1;
        float m = g_mean2[row0 + r];
        float lo = m - MARGIN;
        float ssum = 0.0f;
#pragma unroll 8
        for (int i = 0; i < 64; i++) {
            float s = tr[r * TRS + h + 2 * i];
            float e = __expf(s * TEMP_INV);
            float w = (s < m && s > lo) ? 2.0f : 1.0f;
            ssum = fmaf(e, w, ssum);
        }
        rp[tid] = ssum;
    }
    __syncthreads();
    if (tid < 128)
        g_prow[(size_t)(row0 + tid) * gridDim.x + blockIdx.x] =
            rp[2 * tid] + rp[2 * tid + 1];
    __syncthreads();

    // Col pass (dir 1): anchor = text row col0+c.
    {
        int c = tid >> 1, h = tid & 1;
        float m = g_mean2[BMAX + col0 + c];
        float lo = m - MARGIN;
        float ssum = 0.0f;
#pragma unroll 8
        for (int i = 0; i < 64; i++) {
            float s = tr[(h + 2 * i) * TRS + c];
            float e = __expf(s * TEMP_INV);
            float w = (s < m && s > lo) ? 2.0f : 1.0f;
            ssum = fmaf(e, w, ssum);
        }
        rp[tid] = ssum;
    }
    __syncthreads();
    if (tid < 128)
        g_pcol[(size_t)(col0 + tid) * gridDim.y + blockIdx.y] =
            rp[2 * tid] + rp[2 * tid + 1];
}

// ---------------------------------------------------------------------------
// 4. Final per-row loss: one warp per row. Reduce 32 partials (fixed shuffle
//    tree), subtract the positives' weighted exp terms, sum log1p terms.
// ---------------------------------------------------------------------------
__global__ __launch_bounds__(32) void k_final(int N) {
    int r = blockIdx.x;
    int lane = threadIdx.x;
    int nt = N >> 7;
    float p0 = (lane < nt) ? g_prow[(size_t)r * nt + lane] : 0.0f;
    float p1 = (lane < nt) ? g_pcol[(size_t)r * nt + lane] : 0.0f;
    float neg0 = warpSum(p0);
    float neg1 = warpSum(p1);
    if (lane == 0) {
        int np = g_np[r];
        float m0 = g_mean2[r], m1 = g_mean2[BMAX + r];
        float lo0 = m0 - MARGIN, lo1 = m1 - MARGIN;
        float sub0 = 0.0f, sub1 = 0.0f;
        for (int k = 0; k < np; k++) {
            float d0 = g_pd0[r * MAXP + k], d1 = g_pd1[r * MAXP + k];
            sub0 += ((d0 < m0 && d0 > lo0) ? 2.0f : 1.0f) * __expf(d0 * TEMP_INV);
            sub1 += ((d1 < m1 && d1 > lo1) ? 2.0f : 1.0f) * __expf(d1 * TEMP_INV);
        }
        float na0 = neg0 - sub0, na1 = neg1 - sub1;
        float ls0 = 0.0f, ls1 = 0.0f;
        for (int k = 0; k < np; k++) {
            ls0 += log1pf(na0 * __expf(-g_pd0[r * MAXP + k] * TEMP_INV));
            ls1 += log1pf(na1 * __expf(-g_pd1[r * MAXP + k] * TEMP_INV));
        }
        bool valid = (np > 0) && (np < N);
        g_lossA[r] = valid ? ls0 : 0.0f;
        g_lossB[r] = valid ? ls1 : 0.0f;
    }
}

// ---------------------------------------------------------------------------
// 5. Finalize: single block reduces partials to scalar loss
// ---------------------------------------------------------------------------
__global__ __launch_bounds__(256) void k_finalize(float* __restrict__ out, int N) {
    __shared__ float sred[8];
    float a = 0.0f, b = 0.0f, c = 0.0f;
    for (int i = threadIdx.x; i < N; i += 256) {
        a += g_lossA[i];
        b += g_lossB[i];
        c += g_cnt[i];
    }
    float sa = blockSum(a, sred, 8);
    float sb = blockSum(b, sred, 8);
    float sc = blockSum(c, sred, 8);
    if (threadIdx.x == 0) {
        float loss = (sc > 0.0f) ? (sa + sb) / (2.0f * fmaxf(sc, 1.0f)) : 0.0f;
        out[0] = loss;
    }
}

// ---------------------------------------------------------------------------
// Launch: kernel launches only (graph-capture safe, allocation-free).
// ---------------------------------------------------------------------------
extern "C" void kernel_launch(void* const* d_in, const int* in_sizes, int n_in,
                              void* d_out, int out_size) {
    const float* vis = (const float*)d_in[0];
    const float* txt = (const float*)d_in[1];
    const void* ids = d_in[2];
    float* out = (float*)d_out;

    int B = in_sizes[2];
    int D = in_sizes[0] / B;
    if (B > BMAX) B = BMAX;
    if (D > DMAX) D = DMAX;

    cudaFuncSetAttribute(k_gemm_tf32,
                         cudaFuncAttributeMaxDynamicSharedMemorySize, GEMM_SMEM);

    dim3 pgrid(B, 3);
    k_pre<<<pgrid, 256>>>(vis, txt, (const int*)ids, B, D);

    k_pairs<<<B, 128>>>(B, D);

    dim3 ggrid(B / 128, B / 128);
    k_gemm_tf32<<<ggrid, 256, GEMM_SMEM>>>(B, D);

    k_final<<<B, 32>>>(B);

    k_finalize<<<1, 256>>>(out, B);
}

// round 14
// speedup vs baseline: 1.3519x; 1.3519x over previous
#include <cuda_runtime.h>
#include <cuda_bf16.h>
#include <math.h>
#include <stdint.h>

// ---------------------------------------------------------------------------
// Problem constants (fixed instance: B=4096, D=512). Scratch lives in
// __device__ globals. sim is never materialized; GEMM inputs are bf16
// (precision audit in round notes: final rel_err est ~1e-5 vs 1e-3 gate).
// ---------------------------------------------------------------------------
#define BMAX 4096
#define DMAX 512
#define TEMP_INV (1.0f / 0.07f)
#define MARGIN 0.2f
#define MAXP 64
#define NBUCK 2048
#define NT_MAX 32

static __device__ __nv_bfloat16 g_vh[BMAX * DMAX];   // normalized vision (bf16)
static __device__ __nv_bfloat16 g_th[BMAX * DMAX];   // normalized text (bf16)
static __device__ int   g_ids32[BMAX];
static __device__ int   g_bcnt[NBUCK];
static __device__ int   g_bstart[NBUCK + 1];
static __device__ int   g_bitem[BMAX];
static __device__ int   g_np[BMAX];
static __device__ float g_mean2[2 * BMAX];
static __device__ float g_pd0[BMAX * MAXP];
static __device__ float g_pd1[BMAX * MAXP];
static __device__ float g_prow[(size_t)BMAX * NT_MAX];
static __device__ float g_pcol[(size_t)BMAX * NT_MAX];
static __device__ float g_lossA[BMAX];
static __device__ float g_lossB[BMAX];
static __device__ float g_cnt[BMAX];

// ---------------------------------------------------------------------------
// Reductions
// ---------------------------------------------------------------------------
__device__ __forceinline__ float warpSum(float v) {
#pragma unroll
    for (int o = 16; o; o >>= 1) v += __shfl_down_sync(0xffffffffu, v, o);
    return v;
}

__device__ __forceinline__ float blockSum(float v, float* sred, int nwarp) {
    v = warpSum(v);
    int w = threadIdx.x >> 5, l = threadIdx.x & 31;
    if (l == 0) sred[w] = v;
    __syncthreads();
    if (threadIdx.x < 32) {
        float x = (l < nwarp) ? sred[l] : 0.0f;
        x = warpSum(x);
        if (l == 0) sred[0] = x;
    }
    __syncthreads();
    float r = sred[0];
    __syncthreads();
    return r;
}

// ---------------------------------------------------------------------------
// 1. Combined pre-pass, grid (B, 3), 256 threads:
//    y = 0/1 : L2-normalize row x of vision/text -> bf16 (one float2 pass).
//    y = 2   : block x == 0 builds the id table; other x exit.
// ---------------------------------------------------------------------------
__global__ __launch_bounds__(256) void k_pre(const float* __restrict__ vis,
                                             const float* __restrict__ txt,
                                             const int* __restrict__ w,
                                             int n, int D) {
    int tid = threadIdx.x;
    if (blockIdx.y < 2) {
        __shared__ float sred[8];
        int row = blockIdx.x, which = blockIdx.y;
        const float* in = which ? txt : vis;
        __nv_bfloat16* out = which ? g_th : g_vh;
        const float* r = in + (size_t)row * D;
        float ss = 0.0f;
        for (int j = tid * 2; j < D; j += 512) {
            float2 v = *(const float2*)&r[j];
            ss += v.x * v.x + v.y * v.y;
        }
        float tot = blockSum(ss, sred, 8);
        float inv = 1.0f / fmaxf(sqrtf(tot), 1e-12f);
        for (int j = tid * 2; j < D; j += 512) {
            float2 v = *(const float2*)&r[j];
            __nv_bfloat162 h = __floats2bfloat162_rn(v.x * inv, v.y * inv);
            *(__nv_bfloat162*)&out[(size_t)row * D + j] = h;
        }
        return;
    }
    if (blockIdx.x != 0) return;

    // ---- id-table build (single block) ----
    __shared__ int flag;
    __shared__ int warp_tot[8];
    __shared__ int warp_base[8];
    if (tid == 0) flag = 0;
    __syncthreads();
    for (int j = tid * 2 + 1; j < n; j += 512)
        if (w[j] != 0) flag = 1;   // benign race
    __syncthreads();
    int mode = flag ? 0 : 1;       // 0 = int32, 1 = int64
    for (int j = tid; j < n; j += 256)
        g_ids32[j] = mode ? (int)((const long long*)w)[j] : w[j];
    for (int b = tid; b < NBUCK; b += 256) g_bcnt[b] = 0;
    __syncthreads();
    for (int j = tid; j < n; j += 256)
        atomicAdd(&g_bcnt[g_ids32[j] & (NBUCK - 1)], 1);
    __syncthreads();
    int base = tid * (NBUCK / 256);
    int pre[NBUCK / 256];
    int loc = 0;
#pragma unroll
    for (int k = 0; k < NBUCK / 256; k++) { pre[k] = loc; loc += g_bcnt[base + k]; }
    int lane = tid & 31, wd = tid >> 5;
    int v = loc;
#pragma unroll
    for (int o = 1; o < 32; o <<= 1) {
        int t = __shfl_up_sync(0xffffffffu, v, o);
        if (lane >= o) v += t;
    }
    if (lane == 31) warp_tot[wd] = v;
    __syncthreads();
    if (tid == 0) {
        int a = 0;
        for (int i = 0; i < 8; i++) { warp_base[i] = a; a += warp_tot[i]; }
    }
    __syncthreads();
    int excl = warp_base[wd] + v - loc;
#pragma unroll
    for (int k = 0; k < NBUCK / 256; k++) g_bstart[base + k] = excl + pre[k];
    if (tid == 0) g_bstart[NBUCK] = n;
    __syncthreads();
    for (int b = tid; b < NBUCK; b += 256) g_bcnt[b] = g_bstart[b];
    __syncthreads();
    for (int j = tid; j < n; j += 256) {
        int b = g_ids32[j] & (NBUCK - 1);
        int p = atomicAdd(&g_bcnt[b], 1);
        g_bitem[p] = j;
    }
}

// ---------------------------------------------------------------------------
// 2. Pairs: one block (128 threads) per anchor row. Positive dots computed in
//    fp32 FROM THE bf16-ROUNDED inputs (matches GEMM operand values so the
//    later subtraction cancels to ~1e-6), plus per-direction mean_pos.
// ---------------------------------------------------------------------------
__global__ __launch_bounds__(128) void k_pairs(int N, int D) {
    __shared__ float sred[4];
    __shared__ int s_pos[MAXP];
    __shared__ int s_np;
    int r = blockIdx.x;
    int tid = threadIdx.x;
    int myid = g_ids32[r];

    if (tid == 0) {
        int b = myid & (NBUCK - 1);
        int np = 0;
        for (int p = g_bstart[b]; p < g_bstart[b + 1]; p++) {
            int j = g_bitem[p];
            if (g_ids32[j] == myid && np < MAXP) s_pos[np++] = j;
        }
        for (int i = 1; i < np; i++) {
            int x = s_pos[i], k = i - 1;
            while (k >= 0 && s_pos[k] > x) { s_pos[k + 1] = s_pos[k]; k--; }
            s_pos[k + 1] = x;
        }
        s_np = np;
    }
    __syncthreads();
    int np = s_np;
    const __nv_bfloat162* vr = (const __nv_bfloat162*)&g_vh[(size_t)r * D];
    const __nv_bfloat162* tr = (const __nv_bfloat162*)&g_th[(size_t)r * D];
    float m0 = 0.0f, m1 = 0.0f;
    for (int k = 0; k < np; k++) {
        int j = s_pos[k];
        const __nv_bfloat162* vj = (const __nv_bfloat162*)&g_vh[(size_t)j * D];
        const __nv_bfloat162* tj = (const __nv_bfloat162*)&g_th[(size_t)j * D];
        float p0 = 0.0f, p1 = 0.0f;
        for (int d = tid; d < D / 2; d += 128) {
            float2 a0 = __bfloat1622float2(vr[d]);
            float2 b0 = __bfloat1622float2(tj[d]);
            p0 += a0.x * b0.x + a0.y * b0.y;
            float2 a1 = __bfloat1622float2(vj[d]);
            float2 b1 = __bfloat1622float2(tr[d]);
            p1 += a1.x * b1.x + a1.y * b1.y;
        }
        float d0 = blockSum(p0, sred, 4);
        float d1 = blockSum(p1, sred, 4);
        if (tid == 0) { g_pd0[r * MAXP + k] = d0; g_pd1[r * MAXP + k] = d1; }
        m0 += d0; m1 += d1;
    }
    if (tid == 0) {
        float fn = fmaxf((float)np, 1.0f);
        g_mean2[r] = m0 / fn;
        g_mean2[BMAX + r] = m1 / fn;
        g_np[r] = np;
        g_cnt[r] = (float)np;
    }
}

// ---------------------------------------------------------------------------
// 3. Tensor-core GEMM NT (bf16 mma.m16n8k16 + ldmatrix) with FUSED loss
//    reduction epilogue. Smem rows: 32 bf16 = 64 B + 16 B pad = 80 B stride
//    (conflict-free for both cp.async fills and ldmatrix 16B-row reads).
// ---------------------------------------------------------------------------
#define SMSB 80                        // smem row stride in BYTES
#define STAGE_B (2 * 128 * SMSB)       // A + B stage bytes (20480)
#define TRS 133
#define GEMM_SMEM (128 * TRS * 4)      // 68096 B (> 2 stages = 40960 B)

__device__ __forceinline__ void cp16s(uint32_t dst, const void* src) {
    asm volatile("cp.async.cg.shared.global [%0], [%1], 16;" :: "r"(dst), "l"(src));
}

__device__ __forceinline__ void ldm_x4(uint32_t* r, uint32_t addr) {
    asm volatile("ldmatrix.sync.aligned.m8n8.x4.shared.b16 {%0,%1,%2,%3}, [%4];"
                 : "=r"(r[0]), "=r"(r[1]), "=r"(r[2]), "=r"(r[3]) : "r"(addr));
}

__device__ __forceinline__ void mma_bf16(float* c, const uint32_t* a,
                                         uint32_t b0, uint32_t b1) {
    asm("mma.sync.aligned.m16n8k16.row.col.f32.bf16.bf16.f32 "
        "{%0,%1,%2,%3}, {%4,%5,%6,%7}, {%8,%9}, {%0,%1,%2,%3};"
        : "+f"(c[0]), "+f"(c[1]), "+f"(c[2]), "+f"(c[3])
        : "r"(a[0]), "r"(a[1]), "r"(a[2]), "r"(a[3]), "r"(b0), "r"(b1));
}

__global__ __launch_bounds__(256, 2) void k_gemm_bf16(int N, int D) {
    extern __shared__ float sm[];
    __shared__ float rp[256];
    uint32_t smb = (uint32_t)__cvta_generic_to_shared(sm);

    const __nv_bfloat16* __restrict__ A = g_vh;
    const __nv_bfloat16* __restrict__ Bm = g_th;
    int tid = threadIdx.x;
    int wid = tid >> 5, lane = tid & 31;
    int mo = (wid >> 2) * 64;          // warp m offset: 0 or 64
    int no = (wid & 3) * 32;           // warp n offset: 0,32,64,96
    int row0 = blockIdx.y * 128, col0 = blockIdx.x * 128;

    // ldmatrix lane mapping (same byte quadrants as the verified tf32 path):
    // tile = lane>>3 covers (rows 0-7 / 8-15) x (bytes 0-15 / 16-31).
    int tile = lane >> 3, trow = lane & 7;
    int ld_row = trow + (tile & 1) * 8;
    int ld_kofB = (tile >> 1) * 16;    // byte offset within row

    float acc[4][4][4];
#pragma unroll
    for (int ms = 0; ms < 4; ms++)
#pragma unroll
        for (int ns = 0; ns < 4; ns++)
#pragma unroll
            for (int q = 0; q < 4; q++) acc[ms][ns][q] = 0.0f;

    const int KT = D >> 5;   // 32-element k tiles

    // Fill: per matrix 512 16B-chunks (128 rows x 4), 2 per thread.
#define FILL(sidx, kt_) do {                                                   \
        uint32_t sa = smb + (uint32_t)(sidx) * STAGE_B;                        \
        uint32_t sb = sa + 128 * SMSB;                                         \
        int kb = (kt_) << 5;                                                   \
        _Pragma("unroll")                                                      \
        for (int q = 0; q < 2; q++) {                                          \
            int f = tid + q * 256;                                             \
            int rr = f >> 2, c16 = f & 3;                                      \
            cp16s(sa + (uint32_t)(rr * SMSB + c16 * 16),                       \
                  &A[(size_t)(row0 + rr) * D + kb + c16 * 8]);                 \
            cp16s(sb + (uint32_t)(rr * SMSB + c16 * 16),                       \
                  &Bm[(size_t)(col0 + rr) * D + kb + c16 * 8]);                \
        }                                                                      \
        asm volatile("cp.async.commit_group;");                                \
    } while (0)

    FILL(0, 0);
    if (KT > 1) FILL(1, 1);

    for (int kt = 0; kt < KT; kt++) {
        int s = kt & 1;
        if (kt + 1 < KT) asm volatile("cp.async.wait_group 1;");
        else             asm volatile("cp.async.wait_group 0;");
        __syncthreads();

        uint32_t sa = smb + (uint32_t)s * STAGE_B;
        uint32_t sb = sa + 128 * SMSB;
        uint32_t a_base = sa + (uint32_t)((mo + ld_row) * SMSB + ld_kofB);
        uint32_t b_base = sb + (uint32_t)((no + ld_row) * SMSB + ld_kofB);

#pragma unroll
        for (int kk = 0; kk < 2; kk++) {     // two k16 steps cover K=32
            uint32_t a[4][4], b[2][4];
#pragma unroll
            for (int ms = 0; ms < 4; ms++)
                ldm_x4(a[ms], a_base + (uint32_t)(ms * 16 * SMSB + kk * 32));
#pragma unroll
            for (int g = 0; g < 2; g++)      // n-groups 0-15, 16-31
                ldm_x4(b[g], b_base + (uint32_t)(g * 16 * SMSB + kk * 32));
            // b[g] regs: {n-sub 2g k0-7, n-sub 2g+1 k0-7, n-sub 2g k8-15, ...}
#pragma unroll
            for (int ms = 0; ms < 4; ms++)
#pragma unroll
                for (int g = 0; g < 2; g++) {
                    mma_bf16(acc[ms][g * 2],     a[ms], b[g][0], b[g][2]);
                    mma_bf16(acc[ms][g * 2 + 1], a[ms], b[g][1], b[g][3]);
                }
        }
        __syncthreads();
        if (kt + 2 < KT) FILL(s, kt + 2);
    }

    // ---- Fused epilogue: stage tile, reduce both directions ----
    float* tr = sm;
    int lq = lane >> 2, lm4 = lane & 3;
#pragma unroll
    for (int ms = 0; ms < 4; ms++) {
        int r = mo + ms * 16 + lq;
#pragma unroll
        for (int ns = 0; ns < 4; ns++) {
            int c = no + ns * 8 + 2 * lm4;
            tr[r * TRS + c]           = acc[ms][ns][0];
            tr[r * TRS + c + 1]       = acc[ms][ns][1];
            tr[(r + 8) * TRS + c]     = acc[ms][ns][2];
            tr[(r + 8) * TRS + c + 1] = acc[ms][ns][3];
        }
    }
    __syncthreads();

    // Row pass (dir 0): anchor = vision row row0+r.
    {
        int r = tid >> 1, h = tid & 1;
        float m = g_mean2[row0 + r];
        float lo = m - MARGIN;
        float ssum = 0.0f;
#pragma unroll 8
        for (int i = 0; i < 64; i++) {
            float s = tr[r * TRS + h + 2 * i];
            float e = __expf(s * TEMP_INV);
            float w = (s < m && s > lo) ? 2.0f : 1.0f;
            ssum = fmaf(e, w, ssum);
        }
        rp[tid] = ssum;
    }
    __syncthreads();
    if (tid < 128)
        g_prow[(size_t)(row0 + tid) * gridDim.x + blockIdx.x] =
            rp[2 * tid] + rp[2 * tid + 1];
    __syncthreads();

    // Col pass (dir 1): anchor = text row col0+c.
    {
        int c = tid >> 1, h = tid & 1;
        float m = g_mean2[BMAX + col0 + c];
        float lo = m - MARGIN;
        float ssum = 0.0f;
#pragma unroll 8
        for (int i = 0; i < 64; i++) {
            float s = tr[(h + 2 * i) * TRS + c];
            float e = __expf(s * TEMP_INV);
            float w = (s < m && s > lo) ? 2.0f : 1.0f;
            ssum = fmaf(e, w, ssum);
        }
        rp[tid] = ssum;
    }
    __syncthreads();
    if (tid < 128)
        g_pcol[(size_t)(col0 + tid) * gridDim.y + blockIdx.y] =
            rp[2 * tid] + rp[2 * tid + 1];
}

// ---------------------------------------------------------------------------
// 4. Final per-row loss: 256-thread blocks, one warp per row (8 rows/block).
// ---------------------------------------------------------------------------
__global__ __launch_bounds__(256) void k_final(int N) {
    int w = threadIdx.x >> 5;
    int lane = threadIdx.x & 31;
    int r = blockIdx.x * 8 + w;
    if (r >= N) return;
    int nt = N >> 7;
    float p0 = (lane < nt) ? g_prow[(size_t)r * nt + lane] : 0.0f;
    float p1 = (lane < nt) ? g_pcol[(size_t)r * nt + lane] : 0.0f;
    float neg0 = warpSum(p0);
    float neg1 = warpSum(p1);
    if (lane == 0) {
        int np = g_np[r];
        float m0 = g_mean2[r], m1 = g_mean2[BMAX + r];
        float lo0 = m0 - MARGIN, lo1 = m1 - MARGIN;
        float sub0 = 0.0f, sub1 = 0.0f;
        for (int k = 0; k < np; k++) {
            float d0 = g_pd0[r * MAXP + k], d1 = g_pd1[r * MAXP + k];
            sub0 += ((d0 < m0 && d0 > lo0) ? 2.0f : 1.0f) * __expf(d0 * TEMP_INV);
            sub1 += ((d1 < m1 && d1 > lo1) ? 2.0f : 1.0f) * __expf(d1 * TEMP_INV);
        }
        float na0 = neg0 - sub0, na1 = neg1 - sub1;
        float ls0 = 0.0f, ls1 = 0.0f;
        for (int k = 0; k < np; k++) {
            ls0 += log1pf(na0 * __expf(-g_pd0[r * MAXP + k] * TEMP_INV));
            ls1 += log1pf(na1 * __expf(-g_pd1[r * MAXP + k] * TEMP_INV));
        }
        bool valid = (np > 0) && (np < N);
        g_lossA[r] = valid ? ls0 : 0.0f;
        g_lossB[r] = valid ? ls1 : 0.0f;
    }
}

// ---------------------------------------------------------------------------
// 5. Finalize: single block reduces partials to scalar loss
// ---------------------------------------------------------------------------
__global__ __launch_bounds__(256) void k_finalize(float* __restrict__ out, int N) {
    __shared__ float sred[8];
    float a = 0.0f, b = 0.0f, c = 0.0f;
    for (int i = threadIdx.x; i < N; i += 256) {
        a += g_lossA[i];
        b += g_lossB[i];
        c += g_cnt[i];
    }
    float sa = blockSum(a, sred, 8);
    float sb = blockSum(b, sred, 8);
    float sc = blockSum(c, sred, 8);
    if (threadIdx.x == 0) {
        float loss = (sc > 0.0f) ? (sa + sb) / (2.0f * fmaxf(sc, 1.0f)) : 0.0f;
        out[0] = loss;
    }
}

// ---------------------------------------------------------------------------
// Launch: kernel launches only (graph-capture safe, allocation-free).
// ---------------------------------------------------------------------------
extern "C" void kernel_launch(void* const* d_in, const int* in_sizes, int n_in,
                              void* d_out, int out_size) {
    const float* vis = (const float*)d_in[0];
    const float* txt = (const float*)d_in[1];
    const void* ids = d_in[2];
    float* out = (float*)d_out;

    int B = in_sizes[2];
    int D = in_sizes[0] / B;
    if (B > BMAX) B = BMAX;
    if (D > DMAX) D = DMAX;

    cudaFuncSetAttribute(k_gemm_bf16,
                         cudaFuncAttributeMaxDynamicSharedMemorySize, GEMM_SMEM);

    dim3 pgrid(B, 3);
    k_pre<<<pgrid, 256>>>(vis, txt, (const int*)ids, B, D);

    k_pairs<<<B, 128>>>(B, D);

    dim3 ggrid(B / 128, B / 128);
    k_gemm_bf16<<<ggrid, 256, GEMM_SMEM>>>(B, D);

    k_final<<<(B + 7) / 8, 256>>>(B);

    k_finalize<<<1, 256>>>(out, B);
}

// round 15
// speedup vs baseline: 1.4457x; 1.0694x over previous
#include <cuda_runtime.h>
#include <cuda_bf16.h>
#include <math.h>
#include <stdint.h>

// ---------------------------------------------------------------------------
// Problem constants (fixed instance: B=4096, D=512). Scratch lives in
// __device__ globals. sim is never materialized; GEMM inputs are bf16.
// ---------------------------------------------------------------------------
#define BMAX 4096
#define DMAX 512
#define TEMP_INV (1.0f / 0.07f)
#define MARGIN 0.2f
#define MAXP 64
#define NBUCK 2048
#define NT_MAX 32

static __device__ __nv_bfloat16 g_vh[BMAX * DMAX];   // normalized vision (bf16)
static __device__ __nv_bfloat16 g_th[BMAX * DMAX];   // normalized text (bf16)
static __device__ int   g_ids32[BMAX];
static __device__ int   g_bcnt[NBUCK];
static __device__ int   g_bstart[NBUCK + 1];
static __device__ int   g_bitem[BMAX];
static __device__ int   g_np[BMAX];
static __device__ float g_mean2[2 * BMAX];
static __device__ float g_pd0[BMAX * MAXP];
static __device__ float g_pd1[BMAX * MAXP];
static __device__ float g_prow[(size_t)BMAX * NT_MAX];
static __device__ float g_pcol[(size_t)BMAX * NT_MAX];
static __device__ float g_lossA[BMAX];
static __device__ float g_lossB[BMAX];
static __device__ float g_cnt[BMAX];

// ---------------------------------------------------------------------------
// Reductions
// ---------------------------------------------------------------------------
__device__ __forceinline__ float warpSum(float v) {
#pragma unroll
    for (int o = 16; o; o >>= 1) v += __shfl_down_sync(0xffffffffu, v, o);
    return v;
}

__device__ __forceinline__ float blockSum(float v, float* sred, int nwarp) {
    v = warpSum(v);
    int w = threadIdx.x >> 5, l = threadIdx.x & 31;
    if (l == 0) sred[w] = v;
    __syncthreads();
    if (threadIdx.x < 32) {
        float x = (l < nwarp) ? sred[l] : 0.0f;
        x = warpSum(x);
        if (l == 0) sred[0] = x;
    }
    __syncthreads();
    float r = sred[0];
    __syncthreads();
    return r;
}

// ---------------------------------------------------------------------------
// 1. Combined pre-pass, grid (B, 3), 256 threads:
//    y = 0/1 : L2-normalize row x of vision/text -> bf16 (one float2 pass).
//    y = 2   : block x == 0 builds the id table; other x exit.
// ---------------------------------------------------------------------------
__global__ __launch_bounds__(256) void k_pre(const float* __restrict__ vis,
                                             const float* __restrict__ txt,
                                             const int* __restrict__ w,
                                             int n, int D) {
    int tid = threadIdx.x;
    if (blockIdx.y < 2) {
        __shared__ float sred[8];
        int row = blockIdx.x, which = blockIdx.y;
        const float* in = which ? txt : vis;
        __nv_bfloat16* out = which ? g_th : g_vh;
        const float* r = in + (size_t)row * D;
        float ss = 0.0f;
        for (int j = tid * 2; j < D; j += 512) {
            float2 v = *(const float2*)&r[j];
            ss += v.x * v.x + v.y * v.y;
        }
        float tot = blockSum(ss, sred, 8);
        float inv = 1.0f / fmaxf(sqrtf(tot), 1e-12f);
        for (int j = tid * 2; j < D; j += 512) {
            float2 v = *(const float2*)&r[j];
            __nv_bfloat162 h = __floats2bfloat162_rn(v.x * inv, v.y * inv);
            *(__nv_bfloat162*)&out[(size_t)row * D + j] = h;
        }
        return;
    }
    if (blockIdx.x != 0) return;

    // ---- id-table build (single block) ----
    __shared__ int flag;
    __shared__ int warp_tot[8];
    __shared__ int warp_base[8];
    if (tid == 0) flag = 0;
    __syncthreads();
    for (int j = tid * 2 + 1; j < n; j += 512)
        if (w[j] != 0) flag = 1;   // benign race
    __syncthreads();
    int mode = flag ? 0 : 1;       // 0 = int32, 1 = int64
    for (int j = tid; j < n; j += 256)
        g_ids32[j] = mode ? (int)((const long long*)w)[j] : w[j];
    for (int b = tid; b < NBUCK; b += 256) g_bcnt[b] = 0;
    __syncthreads();
    for (int j = tid; j < n; j += 256)
        atomicAdd(&g_bcnt[g_ids32[j] & (NBUCK - 1)], 1);
    __syncthreads();
    int base = tid * (NBUCK / 256);
    int pre[NBUCK / 256];
    int loc = 0;
#pragma unroll
    for (int k = 0; k < NBUCK / 256; k++) { pre[k] = loc; loc += g_bcnt[base + k]; }
    int lane = tid & 31, wd = tid >> 5;
    int v = loc;
#pragma unroll
    for (int o = 1; o < 32; o <<= 1) {
        int t = __shfl_up_sync(0xffffffffu, v, o);
        if (lane >= o) v += t;
    }
    if (lane == 31) warp_tot[wd] = v;
    __syncthreads();
    if (tid == 0) {
        int a = 0;
        for (int i = 0; i < 8; i++) { warp_base[i] = a; a += warp_tot[i]; }
    }
    __syncthreads();
    int excl = warp_base[wd] + v - loc;
#pragma unroll
    for (int k = 0; k < NBUCK / 256; k++) g_bstart[base + k] = excl + pre[k];
    if (tid == 0) g_bstart[NBUCK] = n;
    __syncthreads();
    for (int b = tid; b < NBUCK; b += 256) g_bcnt[b] = g_bstart[b];
    __syncthreads();
    for (int j = tid; j < n; j += 256) {
        int b = g_ids32[j] & (NBUCK - 1);
        int p = atomicAdd(&g_bcnt[b], 1);
        g_bitem[p] = j;
    }
}

// ---------------------------------------------------------------------------
// 2. Pairs: one block (128 threads) per anchor row. Positive dots in fp32
//    FROM THE bf16-ROUNDED inputs, plus per-direction mean_pos.
// ---------------------------------------------------------------------------
__global__ __launch_bounds__(128) void k_pairs(int N, int D) {
    __shared__ float sred[4];
    __shared__ int s_pos[MAXP];
    __shared__ int s_np;
    int r = blockIdx.x;
    int tid = threadIdx.x;
    int myid = g_ids32[r];

    if (tid == 0) {
        int b = myid & (NBUCK - 1);
        int np = 0;
        for (int p = g_bstart[b]; p < g_bstart[b + 1]; p++) {
            int j = g_bitem[p];
            if (g_ids32[j] == myid && np < MAXP) s_pos[np++] = j;
        }
        for (int i = 1; i < np; i++) {
            int x = s_pos[i], k = i - 1;
            while (k >= 0 && s_pos[k] > x) { s_pos[k + 1] = s_pos[k]; k--; }
            s_pos[k + 1] = x;
        }
        s_np = np;
    }
    __syncthreads();
    int np = s_np;
    const __nv_bfloat162* vr = (const __nv_bfloat162*)&g_vh[(size_t)r * D];
    const __nv_bfloat162* tr = (const __nv_bfloat162*)&g_th[(size_t)r * D];
    float m0 = 0.0f, m1 = 0.0f;
    for (int k = 0; k < np; k++) {
        int j = s_pos[k];
        const __nv_bfloat162* vj = (const __nv_bfloat162*)&g_vh[(size_t)j * D];
        const __nv_bfloat162* tj = (const __nv_bfloat162*)&g_th[(size_t)j * D];
        float p0 = 0.0f, p1 = 0.0f;
        for (int d = tid; d < D / 2; d += 128) {
            float2 a0 = __bfloat1622float2(vr[d]);
            float2 b0 = __bfloat1622float2(tj[d]);
            p0 += a0.x * b0.x + a0.y * b0.y;
            float2 a1 = __bfloat1622float2(vj[d]);
            float2 b1 = __bfloat1622float2(tr[d]);
            p1 += a1.x * b1.x + a1.y * b1.y;
        }
        float d0 = blockSum(p0, sred, 4);
        float d1 = blockSum(p1, sred, 4);
        if (tid == 0) { g_pd0[r * MAXP + k] = d0; g_pd1[r * MAXP + k] = d1; }
        m0 += d0; m1 += d1;
    }
    if (tid == 0) {
        float fn = fmaxf((float)np, 1.0f);
        g_mean2[r] = m0 / fn;
        g_mean2[BMAX + r] = m1 / fn;
        g_np[r] = np;
        g_cnt[r] = (float)np;
    }
}

// ---------------------------------------------------------------------------
// 3. Tensor-core GEMM NT (bf16 mma.m16n8k16 + ldmatrix) with FUSED loss
//    reduction epilogue. K staged 64-wide: 128 B data + 16 B pad = 144 B
//    rows (4r-mod-32 bank pattern, conflict-free). Epilogue computes exp
//    ONCE per element: row pass stores e back to smem; col pass classifies
//    in e-space (exp monotone).
// ---------------------------------------------------------------------------
#define SMSB 144                       // smem row stride in BYTES
#define STAGE_B (2 * 128 * SMSB)       // A + B stage bytes (36864)
#define TRS 133
#define GEMM_SMEM (2 * STAGE_B)        // 73728 B (> epilogue 68096 B)

__device__ __forceinline__ void cp16s(uint32_t dst, const void* src) {
    asm volatile("cp.async.cg.shared.global [%0], [%1], 16;" :: "r"(dst), "l"(src));
}

__device__ __forceinline__ void ldm_x4(uint32_t* r, uint32_t addr) {
    asm volatile("ldmatrix.sync.aligned.m8n8.x4.shared.b16 {%0,%1,%2,%3}, [%4];"
                 : "=r"(r[0]), "=r"(r[1]), "=r"(r[2]), "=r"(r[3]) : "r"(addr));
}

__device__ __forceinline__ void mma_bf16(float* c, const uint32_t* a,
                                         uint32_t b0, uint32_t b1) {
    asm("mma.sync.aligned.m16n8k16.row.col.f32.bf16.bf16.f32 "
        "{%0,%1,%2,%3}, {%4,%5,%6,%7}, {%8,%9}, {%0,%1,%2,%3};"
        : "+f"(c[0]), "+f"(c[1]), "+f"(c[2]), "+f"(c[3])
        : "r"(a[0]), "r"(a[1]), "r"(a[2]), "r"(a[3]), "r"(b0), "r"(b1));
}

__global__ __launch_bounds__(256, 2) void k_gemm_bf16(int N, int D) {
    extern __shared__ float sm[];
    __shared__ float rp[256];
    uint32_t smb = (uint32_t)__cvta_generic_to_shared(sm);

    const __nv_bfloat16* __restrict__ A = g_vh;
    const __nv_bfloat16* __restrict__ Bm = g_th;
    int tid = threadIdx.x;
    int wid = tid >> 5, lane = tid & 31;
    int mo = (wid >> 2) * 64;
    int no = (wid & 3) * 32;
    int row0 = blockIdx.y * 128, col0 = blockIdx.x * 128;

    int tile = lane >> 3, trow = lane & 7;
    int ld_row = trow + (tile & 1) * 8;
    int ld_kofB = (tile >> 1) * 16;

    float acc[4][4][4];
#pragma unroll
    for (int ms = 0; ms < 4; ms++)
#pragma unroll
        for (int ns = 0; ns < 4; ns++)
#pragma unroll
            for (int q = 0; q < 4; q++) acc[ms][ns][q] = 0.0f;

    const int KT = D >> 6;   // 64-element k tiles

    // Fill: per matrix 1024 16B-chunks (128 rows x 8), 4 per thread.
#define FILL(sidx, kt_) do {                                                   \
        uint32_t sa = smb + (uint32_t)(sidx) * STAGE_B;                        \
        uint32_t sb = sa + 128 * SMSB;                                         \
        int kb = (kt_) << 6;                                                   \
        _Pragma("unroll")                                                      \
        for (int q = 0; q < 4; q++) {                                          \
            int f = tid + q * 256;                                             \
            int rr = f >> 3, c16 = f & 7;                                      \
            cp16s(sa + (uint32_t)(rr * SMSB + c16 * 16),                       \
                  &A[(size_t)(row0 + rr) * D + kb + c16 * 8]);                 \
            cp16s(sb + (uint32_t)(rr * SMSB + c16 * 16),                       \
                  &Bm[(size_t)(col0 + rr) * D + kb + c16 * 8]);                \
        }                                                                      \
        asm volatile("cp.async.commit_group;");                                \
    } while (0)

    FILL(0, 0);
    if (KT > 1) FILL(1, 1);

    for (int kt = 0; kt < KT; kt++) {
        int s = kt & 1;
        if (kt + 1 < KT) asm volatile("cp.async.wait_group 1;");
        else             asm volatile("cp.async.wait_group 0;");
        __syncthreads();

        uint32_t sa = smb + (uint32_t)s * STAGE_B;
        uint32_t sb = sa + 128 * SMSB;
        uint32_t a_base = sa + (uint32_t)((mo + ld_row) * SMSB + ld_kofB);
        uint32_t b_base = sb + (uint32_t)((no + ld_row) * SMSB + ld_kofB);

#pragma unroll
        for (int kk = 0; kk < 4; kk++) {     // four k16 steps cover K=64
            uint32_t a[4][4], b[2][4];
#pragma unroll
            for (int ms = 0; ms < 4; ms++)
                ldm_x4(a[ms], a_base + (uint32_t)(ms * 16 * SMSB + kk * 32));
#pragma unroll
            for (int g = 0; g < 2; g++)
                ldm_x4(b[g], b_base + (uint32_t)(g * 16 * SMSB + kk * 32));
#pragma unroll
            for (int ms = 0; ms < 4; ms++)
#pragma unroll
                for (int g = 0; g < 2; g++) {
                    mma_bf16(acc[ms][g * 2],     a[ms], b[g][0], b[g][2]);
                    mma_bf16(acc[ms][g * 2 + 1], a[ms], b[g][1], b[g][3]);
                }
        }
        __syncthreads();
        if (kt + 2 < KT) FILL(s, kt + 2);
    }

    // ---- Fused epilogue: stage tile, reduce both directions, exp once ----
    float* tr = sm;
    int lq = lane >> 2, lm4 = lane & 3;
#pragma unroll
    for (int ms = 0; ms < 4; ms++) {
        int r = mo + ms * 16 + lq;
#pragma unroll
        for (int ns = 0; ns < 4; ns++) {
            int c = no + ns * 8 + 2 * lm4;
            tr[r * TRS + c]           = acc[ms][ns][0];
            tr[r * TRS + c + 1]       = acc[ms][ns][1];
            tr[(r + 8) * TRS + c]     = acc[ms][ns][2];
            tr[(r + 8) * TRS + c + 1] = acc[ms][ns][3];
        }
    }
    __syncthreads();

    // Row pass (dir 0): s-space weights; store e back into the tile.
    {
        int r = tid >> 1, h = tid & 1;
        float m = g_mean2[row0 + r];
        float lo = m - MARGIN;
        float ssum = 0.0f;
#pragma unroll 8
        for (int i = 0; i < 64; i++) {
            int idx = r * TRS + h + 2 * i;
            float s = tr[idx];
            float e = __expf(s * TEMP_INV);
            float w = (s < m && s > lo) ? 2.0f : 1.0f;
            ssum = fmaf(e, w, ssum);
            tr[idx] = e;
        }
        rp[tid] = ssum;
    }
    __syncthreads();
    if (tid < 128)
        g_prow[(size_t)(row0 + tid) * gridDim.x + blockIdx.x] =
            rp[2 * tid] + rp[2 * tid + 1];
    __syncthreads();

    // Col pass (dir 1): e-space weights (exp monotone), zero extra exps
    // beyond the two per-thread thresholds.
    {
        int c = tid >> 1, h = tid & 1;
        float m = g_mean2[BMAX + col0 + c];
        float em = __expf(m * TEMP_INV);
        float el = __expf((m - MARGIN) * TEMP_INV);
        float ssum = 0.0f;
#pragma unroll 8
        for (int i = 0; i < 64; i++) {
            float e = tr[(h + 2 * i) * TRS + c];
            float w = (e < em && e > el) ? 2.0f : 1.0f;
            ssum = fmaf(e, w, ssum);
        }
        rp[tid] = ssum;
    }
    __syncthreads();
    if (tid < 128)
        g_pcol[(size_t)(col0 + tid) * gridDim.y + blockIdx.y] =
            rp[2 * tid] + rp[2 * tid + 1];
}

// ---------------------------------------------------------------------------
// 4. Final per-row loss: 256-thread blocks, one warp per row (8 rows/block).
//    dir-1 subtraction uses the SAME e-space compare as the col stream so
//    the positive cancellation stays exact.
// ---------------------------------------------------------------------------
__global__ __launch_bounds__(256) void k_final(int N) {
    int w = threadIdx.x >> 5;
    int lane = threadIdx.x & 31;
    int r = blockIdx.x * 8 + w;
    if (r >= N) return;
    int nt = N >> 7;
    float p0 = (lane < nt) ? g_prow[(size_t)r * nt + lane] : 0.0f;
    float p1 = (lane < nt) ? g_pcol[(size_t)r * nt + lane] : 0.0f;
    float neg0 = warpSum(p0);
    float neg1 = warpSum(p1);
    if (lane == 0) {
        int np = g_np[r];
        float m0 = g_mean2[r], m1 = g_mean2[BMAX + r];
        float lo0 = m0 - MARGIN;
        float em1 = __expf(m1 * TEMP_INV);
        float el1 = __expf((m1 - MARGIN) * TEMP_INV);
        float sub0 = 0.0f, sub1 = 0.0f;
        for (int k = 0; k < np; k++) {
            float d0 = g_pd0[r * MAXP + k], d1 = g_pd1[r * MAXP + k];
            sub0 += ((d0 < m0 && d0 > lo0) ? 2.0f : 1.0f) * __expf(d0 * TEMP_INV);
            float e1 = __expf(d1 * TEMP_INV);
            sub1 += ((e1 < em1 && e1 > el1) ? 2.0f : 1.0f) * e1;
        }
        float na0 = neg0 - sub0, na1 = neg1 - sub1;
        float ls0 = 0.0f, ls1 = 0.0f;
        for (int k = 0; k < np; k++) {
            ls0 += log1pf(na0 * __expf(-g_pd0[r * MAXP + k] * TEMP_INV));
            ls1 += log1pf(na1 * __expf(-g_pd1[r * MAXP + k] * TEMP_INV));
        }
        bool valid = (np > 0) && (np < N);
        g_lossA[r] = valid ? ls0 : 0.0f;
        g_lossB[r] = valid ? ls1 : 0.0f;
    }
}

// ---------------------------------------------------------------------------
// 5. Finalize: single block reduces partials to scalar loss
// ---------------------------------------------------------------------------
__global__ __launch_bounds__(256) void k_finalize(float* __restrict__ out, int N) {
    __shared__ float sred[8];
    float a = 0.0f, b = 0.0f, c = 0.0f;
    for (int i = threadIdx.x; i < N; i += 256) {
        a += g_lossA[i];
        b += g_lossB[i];
        c += g_cnt[i];
    }
    float sa = blockSum(a, sred, 8);
    float sb = blockSum(b, sred, 8);
    float sc = blockSum(c, sred, 8);
    if (threadIdx.x == 0) {
        float loss = (sc > 0.0f) ? (sa + sb) / (2.0f * fmaxf(sc, 1.0f)) : 0.0f;
        out[0] = loss;
    }
}

// ---------------------------------------------------------------------------
// Launch: kernel launches only (graph-capture safe, allocation-free).
// ---------------------------------------------------------------------------
extern "C" void kernel_launch(void* const* d_in, const int* in_sizes, int n_in,
                              void* d_out, int out_size) {
    const float* vis = (const float*)d_in[0];
    const float* txt = (const float*)d_in[1];
    const void* ids = d_in[2];
    float* out = (float*)d_out;

    int B = in_sizes[2];
    int D = in_sizes[0] / B;
    if (B > BMAX) B = BMAX;
    if (D > DMAX) D = DMAX;

    cudaFuncSetAttribute(k_gemm_bf16,
                         cudaFuncAttributeMaxDynamicSharedMemorySize, GEMM_SMEM);

    dim3 pgrid(B, 3);
    k_pre<<<pgrid, 256>>>(vis, txt, (const int*)ids, B, D);

    k_pairs<<<B, 128>>>(B, D);

    dim3 ggrid(B / 128, B / 128);
    k_gemm_bf16<<<ggrid, 256, GEMM_SMEM>>>(B, D);

    k_final<<<(B + 7) / 8, 256>>>(B);

    k_finalize<<<1, 256>>>(out, B);
}

// round 16
// speedup vs baseline: 1.5188x; 1.0505x over previous
#include <cuda_runtime.h>
#include <cuda_bf16.h>
#include <math.h>
#include <stdint.h>

// ---------------------------------------------------------------------------
// Problem constants (fixed instance: B=4096, D=512). Scratch lives in
// __device__ globals. sim is never materialized; GEMM inputs are bf16.
// ---------------------------------------------------------------------------
#define BMAX 4096
#define DMAX 512
#define TEMP_INV (1.0f / 0.07f)
#define MARGIN 0.2f
#define MAXP 64
#define NBUCK 2048
#define NT_MAX 32

static __device__ __nv_bfloat16 g_vh[BMAX * DMAX];   // normalized vision (bf16)
static __device__ __nv_bfloat16 g_th[BMAX * DMAX];   // normalized text (bf16)
static __device__ int   g_ids32[BMAX];
static __device__ int   g_bcnt[NBUCK];
static __device__ int   g_bstart[NBUCK + 1];
static __device__ int   g_bitem[BMAX];
static __device__ int   g_np[BMAX];
static __device__ float g_mean2[2 * BMAX];
static __device__ float g_pd0[BMAX * MAXP];
static __device__ float g_pd1[BMAX * MAXP];
static __device__ float g_prow[(size_t)BMAX * NT_MAX];
static __device__ float g_pcol[(size_t)BMAX * NT_MAX];
static __device__ float g_lossA[BMAX];
static __device__ float g_lossB[BMAX];
static __device__ float g_cnt[BMAX];

// ---------------------------------------------------------------------------
// Reductions
// ---------------------------------------------------------------------------
__device__ __forceinline__ float warpSum(float v) {
#pragma unroll
    for (int o = 16; o; o >>= 1) v += __shfl_down_sync(0xffffffffu, v, o);
    return v;
}

__device__ __forceinline__ float blockSum(float v, float* sred, int nwarp) {
    v = warpSum(v);
    int w = threadIdx.x >> 5, l = threadIdx.x & 31;
    if (l == 0) sred[w] = v;
    __syncthreads();
    if (threadIdx.x < 32) {
        float x = (l < nwarp) ? sred[l] : 0.0f;
        x = warpSum(x);
        if (l == 0) sred[0] = x;
    }
    __syncthreads();
    float r = sred[0];
    __syncthreads();
    return r;
}

// ---------------------------------------------------------------------------
// 1. Combined pre-pass, grid (B, 3), 256 threads:
//    y = 0/1 : L2-normalize row x of vision/text -> bf16 (one float2 pass).
//    y = 2   : block x == 0 builds the id table; other x exit.
// ---------------------------------------------------------------------------
__global__ __launch_bounds__(256) void k_pre(const float* __restrict__ vis,
                                             const float* __restrict__ txt,
                                             const int* __restrict__ w,
                                             int n, int D) {
    int tid = threadIdx.x;
    if (blockIdx.y < 2) {
        __shared__ float sred[8];
        int row = blockIdx.x, which = blockIdx.y;
        const float* in = which ? txt : vis;
        __nv_bfloat16* out = which ? g_th : g_vh;
        const float* r = in + (size_t)row * D;
        float ss = 0.0f;
        for (int j = tid * 2; j < D; j += 512) {
            float2 v = *(const float2*)&r[j];
            ss += v.x * v.x + v.y * v.y;
        }
        float tot = blockSum(ss, sred, 8);
        float inv = 1.0f / fmaxf(sqrtf(tot), 1e-12f);
        for (int j = tid * 2; j < D; j += 512) {
            float2 v = *(const float2*)&r[j];
            __nv_bfloat162 h = __floats2bfloat162_rn(v.x * inv, v.y * inv);
            *(__nv_bfloat162*)&out[(size_t)row * D + j] = h;
        }
        return;
    }
    if (blockIdx.x != 0) return;

    // ---- id-table build (single block) ----
    __shared__ int flag;
    __shared__ int warp_tot[8];
    __shared__ int warp_base[8];
    if (tid == 0) flag = 0;
    __syncthreads();
    for (int j = tid * 2 + 1; j < n; j += 512)
        if (w[j] != 0) flag = 1;   // benign race
    __syncthreads();
    int mode = flag ? 0 : 1;       // 0 = int32, 1 = int64
    for (int j = tid; j < n; j += 256)
        g_ids32[j] = mode ? (int)((const long long*)w)[j] : w[j];
    for (int b = tid; b < NBUCK; b += 256) g_bcnt[b] = 0;
    __syncthreads();
    for (int j = tid; j < n; j += 256)
        atomicAdd(&g_bcnt[g_ids32[j] & (NBUCK - 1)], 1);
    __syncthreads();
    int base = tid * (NBUCK / 256);
    int pre[NBUCK / 256];
    int loc = 0;
#pragma unroll
    for (int k = 0; k < NBUCK / 256; k++) { pre[k] = loc; loc += g_bcnt[base + k]; }
    int lane = tid & 31, wd = tid >> 5;
    int v = loc;
#pragma unroll
    for (int o = 1; o < 32; o <<= 1) {
        int t = __shfl_up_sync(0xffffffffu, v, o);
        if (lane >= o) v += t;
    }
    if (lane == 31) warp_tot[wd] = v;
    __syncthreads();
    if (tid == 0) {
        int a = 0;
        for (int i = 0; i < 8; i++) { warp_base[i] = a; a += warp_tot[i]; }
    }
    __syncthreads();
    int excl = warp_base[wd] + v - loc;
#pragma unroll
    for (int k = 0; k < NBUCK / 256; k++) g_bstart[base + k] = excl + pre[k];
    if (tid == 0) g_bstart[NBUCK] = n;
    __syncthreads();
    for (int b = tid; b < NBUCK; b += 256) g_bcnt[b] = g_bstart[b];
    __syncthreads();
    for (int j = tid; j < n; j += 256) {
        int b = g_ids32[j] & (NBUCK - 1);
        int p = atomicAdd(&g_bcnt[b], 1);
        g_bitem[p] = j;
    }
}

// ---------------------------------------------------------------------------
// 2. Pairs: one block (128 threads) per anchor row. Positive dots in fp32
//    FROM THE bf16-ROUNDED inputs, plus per-direction mean_pos.
// ---------------------------------------------------------------------------
__global__ __launch_bounds__(128) void k_pairs(int N, int D) {
    __shared__ float sred[4];
    __shared__ int s_pos[MAXP];
    __shared__ int s_np;
    int r = blockIdx.x;
    int tid = threadIdx.x;
    int myid = g_ids32[r];

    if (tid == 0) {
        int b = myid & (NBUCK - 1);
        int np = 0;
        for (int p = g_bstart[b]; p < g_bstart[b + 1]; p++) {
            int j = g_bitem[p];
            if (g_ids32[j] == myid && np < MAXP) s_pos[np++] = j;
        }
        for (int i = 1; i < np; i++) {
            int x = s_pos[i], k = i - 1;
            while (k >= 0 && s_pos[k] > x) { s_pos[k + 1] = s_pos[k]; k--; }
            s_pos[k + 1] = x;
        }
        s_np = np;
    }
    __syncthreads();
    int np = s_np;
    const __nv_bfloat162* vr = (const __nv_bfloat162*)&g_vh[(size_t)r * D];
    const __nv_bfloat162* tr = (const __nv_bfloat162*)&g_th[(size_t)r * D];
    float m0 = 0.0f, m1 = 0.0f;
    for (int k = 0; k < np; k++) {
        int j = s_pos[k];
        const __nv_bfloat162* vj = (const __nv_bfloat162*)&g_vh[(size_t)j * D];
        const __nv_bfloat162* tj = (const __nv_bfloat162*)&g_th[(size_t)j * D];
        float p0 = 0.0f, p1 = 0.0f;
        for (int d = tid; d < D / 2; d += 128) {
            float2 a0 = __bfloat1622float2(vr[d]);
            float2 b0 = __bfloat1622float2(tj[d]);
            p0 += a0.x * b0.x + a0.y * b0.y;
            float2 a1 = __bfloat1622float2(vj[d]);
            float2 b1 = __bfloat1622float2(tr[d]);
            p1 += a1.x * b1.x + a1.y * b1.y;
        }
        float d0 = blockSum(p0, sred, 4);
        float d1 = blockSum(p1, sred, 4);
        if (tid == 0) { g_pd0[r * MAXP + k] = d0; g_pd1[r * MAXP + k] = d1; }
        m0 += d0; m1 += d1;
    }
    if (tid == 0) {
        float fn = fmaxf((float)np, 1.0f);
        g_mean2[r] = m0 / fn;
        g_mean2[BMAX + r] = m1 / fn;
        g_np[r] = np;
        g_cnt[r] = (float)np;
    }
}

// ---------------------------------------------------------------------------
// 3. Tensor-core GEMM NT (bf16 mma.m16n8k16 + ldmatrix) with REGISTER-
//    RESIDENT fused loss epilogue: exp on acc registers, shfl-tree row/col
//    partials, tiny smem combine. No tile staging.
// ---------------------------------------------------------------------------
#define SMSB 144                       // smem row stride in BYTES
#define STAGE_B (2 * 128 * SMSB)       // A + B stage bytes (36864)
#define GEMM_SMEM (2 * STAGE_B)        // 73728 B

__device__ __forceinline__ void cp16s(uint32_t dst, const void* src) {
    asm volatile("cp.async.cg.shared.global [%0], [%1], 16;" :: "r"(dst), "l"(src));
}

__device__ __forceinline__ void ldm_x4(uint32_t* r, uint32_t addr) {
    asm volatile("ldmatrix.sync.aligned.m8n8.x4.shared.b16 {%0,%1,%2,%3}, [%4];"
                 : "=r"(r[0]), "=r"(r[1]), "=r"(r[2]), "=r"(r[3]) : "r"(addr));
}

__device__ __forceinline__ void mma_bf16(float* c, const uint32_t* a,
                                         uint32_t b0, uint32_t b1) {
    asm("mma.sync.aligned.m16n8k16.row.col.f32.bf16.bf16.f32 "
        "{%0,%1,%2,%3}, {%4,%5,%6,%7}, {%8,%9}, {%0,%1,%2,%3};"
        : "+f"(c[0]), "+f"(c[1]), "+f"(c[2]), "+f"(c[3])
        : "r"(a[0]), "r"(a[1]), "r"(a[2]), "r"(a[3]), "r"(b0), "r"(b1));
}

__global__ __launch_bounds__(256, 2) void k_gemm_bf16(int N, int D) {
    extern __shared__ float sm[];
    uint32_t smb = (uint32_t)__cvta_generic_to_shared(sm);

    const __nv_bfloat16* __restrict__ A = g_vh;
    const __nv_bfloat16* __restrict__ Bm = g_th;
    int tid = threadIdx.x;
    int wid = tid >> 5, lane = tid & 31;
    int mo = (wid >> 2) * 64;
    int no = (wid & 3) * 32;
    int row0 = blockIdx.y * 128, col0 = blockIdx.x * 128;

    int tile = lane >> 3, trow = lane & 7;
    int ld_row = trow + (tile & 1) * 8;
    int ld_kofB = (tile >> 1) * 16;

    float acc[4][4][4];
#pragma unroll
    for (int ms = 0; ms < 4; ms++)
#pragma unroll
        for (int ns = 0; ns < 4; ns++)
#pragma unroll
            for (int q = 0; q < 4; q++) acc[ms][ns][q] = 0.0f;

    const int KT = D >> 6;   // 64-element k tiles

#define FILL(sidx, kt_) do {                                                   \
        uint32_t sa = smb + (uint32_t)(sidx) * STAGE_B;                        \
        uint32_t sb = sa + 128 * SMSB;                                         \
        int kb = (kt_) << 6;                                                   \
        _Pragma("unroll")                                                      \
        for (int q = 0; q < 4; q++) {                                          \
            int f = tid + q * 256;                                             \
            int rr = f >> 3, c16 = f & 7;                                      \
            cp16s(sa + (uint32_t)(rr * SMSB + c16 * 16),                       \
                  &A[(size_t)(row0 + rr) * D + kb + c16 * 8]);                 \
            cp16s(sb + (uint32_t)(rr * SMSB + c16 * 16),                       \
                  &Bm[(size_t)(col0 + rr) * D + kb + c16 * 8]);                \
        }                                                                      \
        asm volatile("cp.async.commit_group;");                                \
    } while (0)

    FILL(0, 0);
    if (KT > 1) FILL(1, 1);

    for (int kt = 0; kt < KT; kt++) {
        int s = kt & 1;
        if (kt + 1 < KT) asm volatile("cp.async.wait_group 1;");
        else             asm volatile("cp.async.wait_group 0;");
        __syncthreads();

        uint32_t sa = smb + (uint32_t)s * STAGE_B;
        uint32_t sb = sa + 128 * SMSB;
        uint32_t a_base = sa + (uint32_t)((mo + ld_row) * SMSB + ld_kofB);
        uint32_t b_base = sb + (uint32_t)((no + ld_row) * SMSB + ld_kofB);

#pragma unroll
        for (int kk = 0; kk < 4; kk++) {
            uint32_t a[4][4], b[2][4];
#pragma unroll
            for (int ms = 0; ms < 4; ms++)
                ldm_x4(a[ms], a_base + (uint32_t)(ms * 16 * SMSB + kk * 32));
#pragma unroll
            for (int g = 0; g < 2; g++)
                ldm_x4(b[g], b_base + (uint32_t)(g * 16 * SMSB + kk * 32));
#pragma unroll
            for (int ms = 0; ms < 4; ms++)
#pragma unroll
                for (int g = 0; g < 2; g++) {
                    mma_bf16(acc[ms][g * 2],     a[ms], b[g][0], b[g][2]);
                    mma_bf16(acc[ms][g * 2 + 1], a[ms], b[g][1], b[g][3]);
                }
        }
        __syncthreads();
        if (kt + 2 < KT) FILL(s, kt + 2);
    }

    // ---- Register-resident epilogue ----
    __syncthreads();   // all ldmatrix done; stage smem reusable
    float* rowbuf = sm;            // [128][4] per-nwarp row partials
    float* colbuf = sm + 512;      // [128][2] per-mwarp col partials
    float* s_em   = sm + 768;      // [128] exp(m_col/T)
    float* s_el   = sm + 896;      // [128] exp((m_col-M)/T)

    if (tid < 128) {
        float m = g_mean2[BMAX + col0 + tid];
        s_em[tid] = __expf(m * TEMP_INV);
        s_el[tid] = __expf((m - MARGIN) * TEMP_INV);
    }
    __syncthreads();

    int lq = lane >> 2, lm4 = lane & 3;
    // Row means for this thread's 8 rows (s-space thresholds)
    float rmean[4][2];
#pragma unroll
    for (int ms = 0; ms < 4; ms++) {
        rmean[ms][0] = g_mean2[row0 + mo + ms * 16 + lq];
        rmean[ms][1] = g_mean2[row0 + mo + ms * 16 + lq + 8];
    }
    // Col e-space thresholds for this thread's 8 cols
    float cem[4][2], cel[4][2];
#pragma unroll
    for (int ns = 0; ns < 4; ns++) {
#pragma unroll
        for (int par = 0; par < 2; par++) {
            int c = no + ns * 8 + 2 * lm4 + par;
            cem[ns][par] = s_em[c];
            cel[ns][par] = s_el[c];
        }
    }

    float rsum[4][2] = {};
    float csum[4][2] = {};
#pragma unroll
    for (int ms = 0; ms < 4; ms++)
#pragma unroll
        for (int h = 0; h < 2; h++) {
            float m = rmean[ms][h], lo = m - MARGIN;
#pragma unroll
            for (int ns = 0; ns < 4; ns++)
#pragma unroll
                for (int par = 0; par < 2; par++) {
                    float s = acc[ms][ns][h * 2 + par];
                    float e = __expf(s * TEMP_INV);
                    float w0 = (s < m && s > lo) ? 2.0f : 1.0f;
                    rsum[ms][h] = fmaf(e, w0, rsum[ms][h]);
                    float w1 = (e < cem[ns][par] && e > cel[ns][par]) ? 2.0f : 1.0f;
                    csum[ns][par] = fmaf(e, w1, csum[ns][par]);
                }
        }

    // Row partials: reduce over the 4 lanes sharing lq (xor 1, 2)
#pragma unroll
    for (int ms = 0; ms < 4; ms++)
#pragma unroll
        for (int h = 0; h < 2; h++) {
            float v = rsum[ms][h];
            v += __shfl_xor_sync(0xffffffffu, v, 1);
            v += __shfl_xor_sync(0xffffffffu, v, 2);
            if (lm4 == 0)
                rowbuf[(mo + ms * 16 + lq + 8 * h) * 4 + (wid & 3)] = v;
        }
    // Col partials: reduce over the 8 lanes sharing lm4 (xor 4, 8, 16)
#pragma unroll
    for (int ns = 0; ns < 4; ns++)
#pragma unroll
        for (int par = 0; par < 2; par++) {
            float v = csum[ns][par];
            v += __shfl_xor_sync(0xffffffffu, v, 4);
            v += __shfl_xor_sync(0xffffffffu, v, 8);
            v += __shfl_xor_sync(0xffffffffu, v, 16);
            if (lq == 0)
                colbuf[(no + ns * 8 + 2 * lm4 + par) * 2 + (wid >> 2)] = v;
        }
    __syncthreads();

    if (tid < 128) {
        float r = rowbuf[tid * 4] + rowbuf[tid * 4 + 1] +
                  rowbuf[tid * 4 + 2] + rowbuf[tid * 4 + 3];
        g_prow[(size_t)(row0 + tid) * gridDim.x + blockIdx.x] = r;
    } else {
        int c = tid - 128;
        g_pcol[(size_t)(col0 + c) * gridDim.y + blockIdx.y] =
            colbuf[c * 2] + colbuf[c * 2 + 1];
    }
}

// ---------------------------------------------------------------------------
// 4. Final per-row loss: 256-thread blocks, one warp per row (8 rows/block).
//    dir-1 subtraction uses the SAME e-space compare as the epilogue.
// ---------------------------------------------------------------------------
__global__ __launch_bounds__(256) void k_final(int N) {
    int w = threadIdx.x >> 5;
    int lane = threadIdx.x & 31;
    int r = blockIdx.x * 8 + w;
    if (r >= N) return;
    int nt = N >> 7;
    float p0 = (lane < nt) ? g_prow[(size_t)r * nt + lane] : 0.0f;
    float p1 = (lane < nt) ? g_pcol[(size_t)r * nt + lane] : 0.0f;
    float neg0 = warpSum(p0);
    float neg1 = warpSum(p1);
    if (lane == 0) {
        int np = g_np[r];
        float m0 = g_mean2[r], m1 = g_mean2[BMAX + r];
        float lo0 = m0 - MARGIN;
        float em1 = __expf(m1 * TEMP_INV);
        float el1 = __expf((m1 - MARGIN) * TEMP_INV);
        float sub0 = 0.0f, sub1 = 0.0f;
        for (int k = 0; k < np; k++) {
            float d0 = g_pd0[r * MAXP + k], d1 = g_pd1[r * MAXP + k];
            sub0 += ((d0 < m0 && d0 > lo0) ? 2.0f : 1.0f) * __expf(d0 * TEMP_INV);
            float e1 = __expf(d1 * TEMP_INV);
            sub1 += ((e1 < em1 && e1 > el1) ? 2.0f : 1.0f) * e1;
        }
        float na0 = neg0 - sub0, na1 = neg1 - sub1;
        float ls0 = 0.0f, ls1 = 0.0f;
        for (int k = 0; k < np; k++) {
            ls0 += log1pf(na0 * __expf(-g_pd0[r * MAXP + k] * TEMP_INV));
            ls1 += log1pf(na1 * __expf(-g_pd1[r * MAXP + k] * TEMP_INV));
        }
        bool valid = (np > 0) && (np < N);
        g_lossA[r] = valid ? ls0 : 0.0f;
        g_lossB[r] = valid ? ls1 : 0.0f;
    }
}

// ---------------------------------------------------------------------------
// 5. Finalize: single block reduces partials to scalar loss
// ---------------------------------------------------------------------------
__global__ __launch_bounds__(256) void k_finalize(float* __restrict__ out, int N) {
    __shared__ float sred[8];
    float a = 0.0f, b = 0.0f, c = 0.0f;
    for (int i = threadIdx.x; i < N; i += 256) {
        a += g_lossA[i];
        b += g_lossB[i];
        c += g_cnt[i];
    }
    float sa = blockSum(a, sred, 8);
    float sb = blockSum(b, sred, 8);
    float sc = blockSum(c, sred, 8);
    if (threadIdx.x == 0) {
        float loss = (sc > 0.0f) ? (sa + sb) / (2.0f * fmaxf(sc, 1.0f)) : 0.0f;
        out[0] = loss;
    }
}

// ---------------------------------------------------------------------------
// Launch: kernel launches only (graph-capture safe, allocation-free).
// ---------------------------------------------------------------------------
extern "C" void kernel_launch(void* const* d_in, const int* in_sizes, int n_in,
                              void* d_out, int out_size) {
    const float* vis = (const float*)d_in[0];
    const float* txt = (const float*)d_in[1];
    const void* ids = d_in[2];
    float* out = (float*)d_out;

    int B = in_sizes[2];
    int D = in_sizes[0] / B;
    if (B > BMAX) B = BMAX;
    if (D > DMAX) D = DMAX;

    cudaFuncSetAttribute(k_gemm_bf16,
                         cudaFuncAttributeMaxDynamicSharedMemorySize, GEMM_SMEM);

    dim3 pgrid(B, 3);
    k_pre<<<pgrid, 256>>>(vis, txt, (const int*)ids, B, D);

    k_pairs<<<B, 128>>>(B, D);

    dim3 ggrid(B / 128, B / 128);
    k_gemm_bf16<<<ggrid, 256, GEMM_SMEM>>>(B, D);

    k_final<<<(B + 7) / 8, 256>>>(B);

    k_finalize<<<1, 256>>>(out, B);
}